// round 2
// baseline (speedup 1.0000x reference)
#include <cuda_runtime.h>

// Shapes (fixed by the problem)
#define NB 4
#define NN 512
#define ND 2
#define NH 64
#define NO 2

// Scratch (device globals: allocation-free per harness rules)
__device__ float g_u[NB * NN * NH];   // u_i[h] + b_n2e[h]
__device__ float g_v[NB * NN * NH];   // v_j[h]
__device__ float g_s[NB * NN * NH];   // masked edge sums

// ---------------------------------------------------------------------------
// Kernel 1: per-node precompute of u (with bias folded) and v
//   u[node][h] = b_n2e[h] + W[h][0]*x0 + W[h][1]*x1
//   v[node][h] =            W[h][2]*x0 + W[h][3]*x1
// ---------------------------------------------------------------------------
__global__ void __launch_bounds__(256) k_prep(const float* __restrict__ x,
                                              const float* __restrict__ Wn2e,
                                              const float* __restrict__ bn2e) {
    int gid = blockIdx.x * 256 + threadIdx.x;   // NB*NN*NH = 131072 items
    if (gid >= NB * NN * NH) return;
    int node = gid >> 6;
    int h = gid & 63;
    float x0 = x[node * 2 + 0];
    float x1 = x[node * 2 + 1];
    const float* w = Wn2e + h * 4;
    g_u[gid] = bn2e[h] + w[0] * x0 + w[1] * x1;
    g_v[gid] =           w[2] * x0 + w[3] * x1;
}

// ---------------------------------------------------------------------------
// Kernel 2: the heavy part. One CTA per (b, i).
//   s[b,i,h] = sum_j adj[i,j] * relu( W_e2e @ relu(u_i + v_j) + b_e2e )[h]
// Structured as 8 j-tiles of 64: build T[k][j] in SMEM, then a register-tiled
// 64x64x64 fp32 GEMM with fused adj-weighted relu reduction.
// 256 threads = 16(tx over h) x 16(ty over j), 4x4 outputs per thread.
// ---------------------------------------------------------------------------
__global__ void __launch_bounds__(256) k_edge(const float* __restrict__ adj,
                                              const float* __restrict__ We2e,
                                              const float* __restrict__ be2e) {
    __shared__ __align__(16) float Wt[64][68];   // W_e2e transposed: Wt[k][h]
    __shared__ __align__(16) float Tsh[64][68];  // T[k][j] for current tile
    __shared__ float su[64];
    __shared__ float red[16][64];

    int t = threadIdx.x;
    int bi = blockIdx.x;          // b*512 + i
    int b = bi >> 9;
    int i = bi & 511;
    int tx = t & 15;              // h group (4 h each)
    int ty = t >> 4;              // j group (4 j each)

    // Stage W_e2e transposed (one-time)
    for (int idx = t; idx < 64 * 64; idx += 256) {
        Wt[idx & 63][idx >> 6] = We2e[idx];
    }
    if (t < 64) su[t] = g_u[bi * 64 + t];

    float4 b2v = *(const float4*)(be2e + tx * 4);

    float acc0 = 0.f, acc1 = 0.f, acc2 = 0.f, acc3 = 0.f;

    int k0 = t & 63;              // k slot for T building
    int jg = t >> 6;              // j group for T building (4 groups x 16 j)

    const float* adjrow = adj + i * NN;
    const float* vbase = g_v + ((b << 9) << 6);

    for (int jt = 0; jt < 8; ++jt) {
        int jbase = jt << 6;
        __syncthreads();   // previous GEMM done (and first-iter: staging done)

        // Build T[k][j] = relu(u_i[k] + v[b][jbase+j][k])
        #pragma unroll
        for (int p = 0; p < 16; ++p) {
            int jj = jg * 16 + p;
            float val = su[k0] + vbase[((jbase + jj) << 6) + k0];
            Tsh[k0][jj] = fmaxf(val, 0.0f);
        }
        __syncthreads();

        // 64x64x64 GEMM: c[r][q] = sum_k T[4ty+r][k] * W[4tx+q][k]
        float c00 = 0, c01 = 0, c02 = 0, c03 = 0;
        float c10 = 0, c11 = 0, c12 = 0, c13 = 0;
        float c20 = 0, c21 = 0, c22 = 0, c23 = 0;
        float c30 = 0, c31 = 0, c32 = 0, c33 = 0;

        #pragma unroll 16
        for (int kk = 0; kk < 64; ++kk) {
            float4 tv = *(const float4*)&Tsh[kk][ty * 4];
            float4 wv = *(const float4*)&Wt[kk][tx * 4];
            c00 += tv.x * wv.x; c01 += tv.x * wv.y; c02 += tv.x * wv.z; c03 += tv.x * wv.w;
            c10 += tv.y * wv.x; c11 += tv.y * wv.y; c12 += tv.y * wv.z; c13 += tv.y * wv.w;
            c20 += tv.z * wv.x; c21 += tv.z * wv.y; c22 += tv.z * wv.z; c23 += tv.z * wv.w;
            c30 += tv.w * wv.x; c31 += tv.w * wv.y; c32 += tv.w * wv.z; c33 += tv.w * wv.w;
        }

        // Fused epilogue: relu(c + b2) * adj[i, j], accumulate over j
        {
            float a0 = adjrow[jbase + ty * 4 + 0];
            float a1 = adjrow[jbase + ty * 4 + 1];
            float a2 = adjrow[jbase + ty * 4 + 2];
            float a3 = adjrow[jbase + ty * 4 + 3];
            acc0 += a0 * fmaxf(c00 + b2v.x, 0.f) + a1 * fmaxf(c10 + b2v.x, 0.f)
                  + a2 * fmaxf(c20 + b2v.x, 0.f) + a3 * fmaxf(c30 + b2v.x, 0.f);
            acc1 += a0 * fmaxf(c01 + b2v.y, 0.f) + a1 * fmaxf(c11 + b2v.y, 0.f)
                  + a2 * fmaxf(c21 + b2v.y, 0.f) + a3 * fmaxf(c31 + b2v.y, 0.f);
            acc2 += a0 * fmaxf(c02 + b2v.z, 0.f) + a1 * fmaxf(c12 + b2v.z, 0.f)
                  + a2 * fmaxf(c22 + b2v.z, 0.f) + a3 * fmaxf(c32 + b2v.z, 0.f);
            acc3 += a0 * fmaxf(c03 + b2v.w, 0.f) + a1 * fmaxf(c13 + b2v.w, 0.f)
                  + a2 * fmaxf(c23 + b2v.w, 0.f) + a3 * fmaxf(c33 + b2v.w, 0.f);
        }
    }

    // Reduce acc over the 16 ty groups
    red[ty][tx * 4 + 0] = acc0;
    red[ty][tx * 4 + 1] = acc1;
    red[ty][tx * 4 + 2] = acc2;
    red[ty][tx * 4 + 3] = acc3;
    __syncthreads();
    if (t < 64) {
        float s = 0.f;
        #pragma unroll
        for (int yy = 0; yy < 16; ++yy) s += red[yy][t];
        g_s[bi * 64 + t] = s;
    }
}

// ---------------------------------------------------------------------------
// Kernel 3: node head. 128 CTAs x 16 nodes. Layer-at-a-time with the weight
// matrix transposed into one shared buffer (conflict-free reads).
// ---------------------------------------------------------------------------
__global__ void __launch_bounds__(256) k_node(const float* __restrict__ x,
                                              const float* __restrict__ We2n,
                                              const float* __restrict__ be2n,
                                              const float* __restrict__ Wn2n,
                                              const float* __restrict__ bn2n,
                                              const float* __restrict__ Wo1,
                                              const float* __restrict__ bo1,
                                              const float* __restrict__ Wo2,
                                              const float* __restrict__ bo2,
                                              float* __restrict__ out) {
    __shared__ float wbuf[66 * 64];     // transposed weights: wbuf[c][h]
    __shared__ float bufA[16][64];
    __shared__ float bufB[16][64];
    __shared__ float sx[16][2];

    int t = threadIdx.x;
    int g = t >> 6;       // 4 thread groups
    int h = t & 63;
    int nbase = blockIdx.x * 16;

    // stage s and x for 16 nodes
    for (int n = g; n < 16; n += 4) bufA[n][h] = g_s[(nbase + n) * 64 + h];
    if (t < 32) sx[t >> 1][t & 1] = x[(nbase + (t >> 1)) * 2 + (t & 1)];

    // ---- layer 1: h1 = relu(W_e2n @ s + b) ----
    for (int idx = t; idx < 64 * 64; idx += 256)
        wbuf[(idx & 63) * 64 + (idx >> 6)] = We2n[idx];
    __syncthreads();
    {
        float bh = be2n[h];
        for (int n = g; n < 16; n += 4) {
            float acc = bh;
            #pragma unroll 8
            for (int k = 0; k < 64; ++k) acc += wbuf[k * 64 + h] * bufA[n][k];
            bufB[n][h] = fmaxf(acc, 0.f);
        }
    }
    __syncthreads();

    // ---- layer 2: h2 = relu(W_n2n @ h1 + b) ----
    for (int idx = t; idx < 64 * 64; idx += 256)
        wbuf[(idx & 63) * 64 + (idx >> 6)] = Wn2n[idx];
    __syncthreads();
    {
        float bh = bn2n[h];
        for (int n = g; n < 16; n += 4) {
            float acc = bh;
            #pragma unroll 8
            for (int k = 0; k < 64; ++k) acc += wbuf[k * 64 + h] * bufB[n][k];
            bufA[n][h] = fmaxf(acc, 0.f);
        }
    }
    __syncthreads();

    // ---- layer 3: h3 = relu(W_o1 @ cat(x, h2) + b), W_o1 is (64, 66) ----
    for (int idx = t; idx < 66 * 64; idx += 256)
        wbuf[(idx % 66) * 64 + (idx / 66)] = Wo1[idx];
    __syncthreads();
    {
        float bh = bo1[h];
        for (int n = g; n < 16; n += 4) {
            float acc = bh + wbuf[0 * 64 + h] * sx[n][0]
                          + wbuf[1 * 64 + h] * sx[n][1];
            #pragma unroll 8
            for (int k = 0; k < 64; ++k) acc += wbuf[(k + 2) * 64 + h] * bufA[n][k];
            bufB[n][h] = fmaxf(acc, 0.f);
        }
    }
    __syncthreads();

    // ---- output: out = W_o2 @ h3 + b, (2, 64) ----
    if (t < 32) {
        int n = t >> 1;
        int o = t & 1;
        float acc = bo2[o];
        const float* w = Wo2 + o * 64;
        #pragma unroll 8
        for (int k = 0; k < 64; ++k) acc += w[k] * bufB[n][k];
        out[(nbase + n) * 2 + o] = acc;
    }
}

// ---------------------------------------------------------------------------
extern "C" void kernel_launch(void* const* d_in, const int* in_sizes, int n_in,
                              void* d_out, int out_size) {
    const float* input = (const float*)d_in[0];
    const float* adj   = (const float*)d_in[1];
    const float* W_n2e = (const float*)d_in[2];
    const float* b_n2e = (const float*)d_in[3];
    const float* W_e2e = (const float*)d_in[4];
    const float* b_e2e = (const float*)d_in[5];
    const float* W_e2n = (const float*)d_in[6];
    const float* b_e2n = (const float*)d_in[7];
    const float* W_n2n = (const float*)d_in[8];
    const float* b_n2n = (const float*)d_in[9];
    const float* W_o1  = (const float*)d_in[10];
    const float* b_o1  = (const float*)d_in[11];
    const float* W_o2  = (const float*)d_in[12];
    const float* b_o2  = (const float*)d_in[13];
    float* out = (float*)d_out;

    k_prep<<<(NB * NN * NH + 255) / 256, 256>>>(input, W_n2e, b_n2e);
    k_edge<<<NB * NN, 256>>>(adj, W_e2e, b_e2e);
    k_node<<<NB * NN / 16, 256>>>(input, W_e2n, b_e2n, W_n2n, b_n2n,
                                  W_o1, b_o1, W_o2, b_o2, out);
}

// round 6
// speedup vs baseline: 1.7389x; 1.7389x over previous
#include <cuda_runtime.h>
#include <cuda_fp16.h>
#include <cstdint>

// Shapes (fixed)
#define NB 4
#define NN 512
#define ND 2
#define NH 64
#define NO 2

// Scratch
__device__ float g_u[NB * NN * NH];
__device__ float g_v[NB * NN * NH];
__device__ float g_s[NB * NN * NH];

// ---------------------------------------------------------------------------
__device__ __forceinline__ uint32_t smem_u32(const void* p) {
    uint32_t a;
    asm("{ .reg .u64 t; cvta.to.shared.u64 t, %1; cvt.u32.u64 %0, t; }" : "=r"(a) : "l"(p));
    return a;
}
// pack two fp32 -> one fp16x2 register (lo = a, hi = b)
__device__ __forceinline__ uint32_t pack_f16x2(float a, float b) {
    uint32_t r;
    asm("cvt.rn.f16x2.f32 %0, %2, %1;" : "=r"(r) : "f"(a), "f"(b));
    return r;
}
__device__ __forceinline__ void ldsm_x4(uint32_t& a0, uint32_t& a1, uint32_t& a2,
                                        uint32_t& a3, uint32_t addr) {
    asm volatile("ldmatrix.sync.aligned.m8n8.x4.shared.b16 {%0,%1,%2,%3}, [%4];"
                 : "=r"(a0), "=r"(a1), "=r"(a2), "=r"(a3) : "r"(addr));
}
// NON-transposed x2: W stored [n(h)][k] row-major; delivers B fragment for row.col
__device__ __forceinline__ void ldsm_x2(uint32_t& b0, uint32_t& b1, uint32_t addr) {
    asm volatile("ldmatrix.sync.aligned.m8n8.x2.shared.b16 {%0,%1}, [%2];"
                 : "=r"(b0), "=r"(b1) : "r"(addr));
}
__device__ __forceinline__ void mma16816(float& c0, float& c1, float& c2, float& c3,
                                         uint32_t a0, uint32_t a1, uint32_t a2, uint32_t a3,
                                         uint32_t b0, uint32_t b1) {
    asm volatile("mma.sync.aligned.m16n8k16.row.col.f32.f16.f16.f32 "
                 "{%0,%1,%2,%3}, {%4,%5,%6,%7}, {%8,%9}, {%0,%1,%2,%3};"
                 : "+f"(c0), "+f"(c1), "+f"(c2), "+f"(c3)
                 : "r"(a0), "r"(a1), "r"(a2), "r"(a3), "r"(b0), "r"(b1));
}

// SMEM row strides (in halves) — 72 gives conflict-free ldmatrix row access
#define TSTR 72
#define WSTR 72

// ---------------------------------------------------------------------------
// Kernel 1: per-node u (bias folded) and v
// ---------------------------------------------------------------------------
__global__ void __launch_bounds__(256) k_prep(const float* __restrict__ x,
                                              const float* __restrict__ Wn2e,
                                              const float* __restrict__ bn2e) {
    int gid = blockIdx.x * 256 + threadIdx.x;
    if (gid >= NB * NN * NH) return;
    int node = gid >> 6;
    int h = gid & 63;
    float x0 = x[node * 2 + 0];
    float x1 = x[node * 2 + 1];
    const float* w = Wn2e + h * 4;
    g_u[gid] = bn2e[h] + w[0] * x0 + w[1] * x1;
    g_v[gid] =           w[2] * x0 + w[3] * x1;
}

// ---------------------------------------------------------------------------
// Kernel 2: edge GEMM via mma.sync m16n8k16 (fp16 in, fp32 accum).
// One CTA per (b,i), 256 threads = 8 warps; warp w owns m-rows [16w,16w+16).
// 4 j-tiles of 128. Epilogue relu(+b2)*adj fused in registers (no D writeback).
// ---------------------------------------------------------------------------
__global__ void __launch_bounds__(256, 2) k_edge_mma(const float* __restrict__ adj,
                                                     const float* __restrict__ We2e,
                                                     const float* __restrict__ be2e) {
    __shared__ __align__(16) __half Tsh[128 * TSTR];
    __shared__ __align__(16) __half Wsh[64 * WSTR];
    __shared__ float su[64];
    __shared__ float sb2[64];
    __shared__ float red[8][64];

    int t = threadIdx.x;
    int w = t >> 5;
    int lane = t & 31;
    int bi = blockIdx.x;
    int b = bi >> 9;
    int i = bi & 511;

    uint32_t Tb = smem_u32(Tsh);
    uint32_t Wb = smem_u32(Wsh);

    // Stage W_e2e [64h][64k] as fp16 rows of stride WSTR.
    {
        int h = t >> 2;
        int kb = (t & 3) * 16;
        const float* wrow = We2e + h * 64 + kb;
        #pragma unroll
        for (int c = 0; c < 2; ++c) {
            float4 f0 = *(const float4*)(wrow + c * 8);
            float4 f1 = *(const float4*)(wrow + c * 8 + 4);
            uint4 pk;
            pk.x = pack_f16x2(f0.x, f0.y);
            pk.y = pack_f16x2(f0.z, f0.w);
            pk.z = pack_f16x2(f1.x, f1.y);
            pk.w = pack_f16x2(f1.z, f1.w);
            *(uint4*)(Wsh + h * WSTR + kb + c * 8) = pk;
        }
    }
    if (t < 64) {
        su[t]  = g_u[bi * 64 + t];
        sb2[t] = be2e[t];
    }
    __syncthreads();

    const float* adjrow = adj + i * NN;
    const float* vbase = g_v + (b << 9) * 64;

    // Per-thread running sums: sacc[nt*2+c] for h = nt*8 + (lane&3)*2 + c
    float sacc[16];
    #pragma unroll
    for (int q = 0; q < 16; ++q) sacc[q] = 0.f;

    int r0 = lane >> 2;            // row within m16 (and +8)
    // A-fragment ldmatrix address pieces: lane -> row (lane%16), k-half (lane/16)
    int a_row = lane & 15;
    int a_kh = lane >> 4;

    for (int jt = 0; jt < 4; ++jt) {
        int jbase = jt << 7;

        // ---- build T[j][k] = relu(u[k] + v[j][k]), fp16 ----
        {
            int j = t >> 1;
            int kb = (t & 1) * 32;
            const float* vrow = vbase + (jbase + j) * 64 + kb;
            __half* trow = Tsh + j * TSTR + kb;
            #pragma unroll
            for (int c = 0; c < 4; ++c) {
                float4 f0 = *(const float4*)(vrow + c * 8);
                float4 f1 = *(const float4*)(vrow + c * 8 + 4);
                int k0 = kb + c * 8;
                uint4 pk;
                pk.x = pack_f16x2(fmaxf(su[k0 + 0] + f0.x, 0.f), fmaxf(su[k0 + 1] + f0.y, 0.f));
                pk.y = pack_f16x2(fmaxf(su[k0 + 2] + f0.z, 0.f), fmaxf(su[k0 + 3] + f0.w, 0.f));
                pk.z = pack_f16x2(fmaxf(su[k0 + 4] + f1.x, 0.f), fmaxf(su[k0 + 5] + f1.y, 0.f));
                pk.w = pack_f16x2(fmaxf(su[k0 + 6] + f1.z, 0.f), fmaxf(su[k0 + 7] + f1.w, 0.f));
                *(uint4*)(trow + c * 8) = pk;
            }
        }
        __syncthreads();

        // ---- MMA: warp w does m16 x n64 x k64 ----
        float acc[8][4];
        #pragma unroll
        for (int nt = 0; nt < 8; ++nt) {
            acc[nt][0] = 0.f; acc[nt][1] = 0.f; acc[nt][2] = 0.f; acc[nt][3] = 0.f;
        }

        #pragma unroll
        for (int k = 0; k < 4; ++k) {
            uint32_t a0, a1, a2, a3;
            uint32_t a_addr = Tb + (uint32_t)(((w * 16 + a_row) * TSTR + k * 16 + a_kh * 8) * 2);
            ldsm_x4(a0, a1, a2, a3, a_addr);
            #pragma unroll
            for (int nt = 0; nt < 8; ++nt) {
                uint32_t b0, b1;
                uint32_t b_addr = Wb + (uint32_t)(((nt * 8 + (lane & 7)) * WSTR
                                                  + k * 16 + ((lane >> 3) & 1) * 8) * 2);
                ldsm_x2(b0, b1, b_addr);
                mma16816(acc[nt][0], acc[nt][1], acc[nt][2], acc[nt][3],
                         a0, a1, a2, a3, b0, b1);
            }
        }

        // ---- fused epilogue: relu(acc + b2) * adj[j], accumulate ----
        {
            float aj0 = adjrow[jbase + w * 16 + r0];
            float aj1 = adjrow[jbase + w * 16 + r0 + 8];
            #pragma unroll
            for (int nt = 0; nt < 8; ++nt) {
                int h0 = nt * 8 + (lane & 3) * 2;
                float bb0 = sb2[h0];
                float bb1 = sb2[h0 + 1];
                sacc[nt * 2 + 0] += aj0 * fmaxf(acc[nt][0] + bb0, 0.f)
                                  + aj1 * fmaxf(acc[nt][2] + bb0, 0.f);
                sacc[nt * 2 + 1] += aj0 * fmaxf(acc[nt][1] + bb1, 0.f)
                                  + aj1 * fmaxf(acc[nt][3] + bb1, 0.f);
            }
        }
        __syncthreads();   // all warps done reading T before next build
    }

    // ---- reduce: sum over row-groups (lanes with same lane&3) ----
    #pragma unroll
    for (int q = 0; q < 16; ++q) {
        sacc[q] += __shfl_down_sync(0xFFFFFFFFu, sacc[q], 16);
        sacc[q] += __shfl_down_sync(0xFFFFFFFFu, sacc[q], 8);
        sacc[q] += __shfl_down_sync(0xFFFFFFFFu, sacc[q], 4);
    }
    if (lane < 4) {
        #pragma unroll
        for (int nt = 0; nt < 8; ++nt) {
            red[w][nt * 8 + lane * 2 + 0] = sacc[nt * 2 + 0];
            red[w][nt * 8 + lane * 2 + 1] = sacc[nt * 2 + 1];
        }
    }
    __syncthreads();
    if (t < 64) {
        float s = 0.f;
        #pragma unroll
        for (int ww = 0; ww < 8; ++ww) s += red[ww][t];
        g_s[bi * 64 + t] = s;
    }
}

// ---------------------------------------------------------------------------
// Kernel 3: node head (unchanged)
// ---------------------------------------------------------------------------
__global__ void __launch_bounds__(256) k_node(const float* __restrict__ x,
                                              const float* __restrict__ We2n,
                                              const float* __restrict__ be2n,
                                              const float* __restrict__ Wn2n,
                                              const float* __restrict__ bn2n,
                                              const float* __restrict__ Wo1,
                                              const float* __restrict__ bo1,
                                              const float* __restrict__ Wo2,
                                              const float* __restrict__ bo2,
                                              float* __restrict__ out) {
    __shared__ float wbuf[66 * 64];
    __shared__ float bufA[16][64];
    __shared__ float bufB[16][64];
    __shared__ float sx[16][2];

    int t = threadIdx.x;
    int g = t >> 6;
    int h = t & 63;
    int nbase = blockIdx.x * 16;

    for (int n = g; n < 16; n += 4) bufA[n][h] = g_s[(nbase + n) * 64 + h];
    if (t < 32) sx[t >> 1][t & 1] = x[(nbase + (t >> 1)) * 2 + (t & 1)];

    for (int idx = t; idx < 64 * 64; idx += 256)
        wbuf[(idx & 63) * 64 + (idx >> 6)] = We2n[idx];
    __syncthreads();
    {
        float bh = be2n[h];
        for (int n = g; n < 16; n += 4) {
            float acc = bh;
            #pragma unroll 8
            for (int k = 0; k < 64; ++k) acc += wbuf[k * 64 + h] * bufA[n][k];
            bufB[n][h] = fmaxf(acc, 0.f);
        }
    }
    __syncthreads();

    for (int idx = t; idx < 64 * 64; idx += 256)
        wbuf[(idx & 63) * 64 + (idx >> 6)] = Wn2n[idx];
    __syncthreads();
    {
        float bh = bn2n[h];
        for (int n = g; n < 16; n += 4) {
            float acc = bh;
            #pragma unroll 8
            for (int k = 0; k < 64; ++k) acc += wbuf[k * 64 + h] * bufB[n][k];
            bufA[n][h] = fmaxf(acc, 0.f);
        }
    }
    __syncthreads();

    for (int idx = t; idx < 66 * 64; idx += 256)
        wbuf[(idx % 66) * 64 + (idx / 66)] = Wo1[idx];
    __syncthreads();
    {
        float bh = bo1[h];
        for (int n = g; n < 16; n += 4) {
            float acc = bh + wbuf[0 * 64 + h] * sx[n][0]
                          + wbuf[1 * 64 + h] * sx[n][1];
            #pragma unroll 8
            for (int k = 0; k < 64; ++k) acc += wbuf[(k + 2) * 64 + h] * bufA[n][k];
            bufB[n][h] = fmaxf(acc, 0.f);
        }
    }
    __syncthreads();

    if (t < 32) {
        int n = t >> 1;
        int o = t & 1;
        float acc = bo2[o];
        const float* wv = Wo2 + o * 64;
        #pragma unroll 8
        for (int k = 0; k < 64; ++k) acc += wv[k] * bufB[n][k];
        out[(nbase + n) * 2 + o] = acc;
    }
}

// ---------------------------------------------------------------------------
extern "C" void kernel_launch(void* const* d_in, const int* in_sizes, int n_in,
                              void* d_out, int out_size) {
    const float* input = (const float*)d_in[0];
    const float* adj   = (const float*)d_in[1];
    const float* W_n2e = (const float*)d_in[2];
    const float* b_n2e = (const float*)d_in[3];
    const float* W_e2e = (const float*)d_in[4];
    const float* b_e2e = (const float*)d_in[5];
    const float* W_e2n = (const float*)d_in[6];
    const float* b_e2n = (const float*)d_in[7];
    const float* W_n2n = (const float*)d_in[8];
    const float* b_n2n = (const float*)d_in[9];
    const float* W_o1  = (const float*)d_in[10];
    const float* b_o1  = (const float*)d_in[11];
    const float* W_o2  = (const float*)d_in[12];
    const float* b_o2  = (const float*)d_in[13];
    float* out = (float*)d_out;

    k_prep<<<(NB * NN * NH + 255) / 256, 256>>>(input, W_n2e, b_n2e);
    k_edge_mma<<<NB * NN, 256>>>(adj, W_e2e, b_e2e);
    k_node<<<NB * NN / 16, 256>>>(input, W_e2n, b_e2n, W_n2n, b_n2n,
                                  W_o1, b_o1, W_o2, b_o2, out);
}

// round 7
// speedup vs baseline: 1.8472x; 1.0622x over previous
#include <cuda_runtime.h>
#include <cuda_fp16.h>
#include <cstdint>

// Shapes (fixed)
#define NB 4
#define NN 512
#define ND 2
#define NH 64
#define NO 2

// Scratch
__device__ float g_u[NB * NN * NH];
__device__ float g_v[NB * NN * NH];
__device__ float g_s[NB * NN * NH];

// ---------------------------------------------------------------------------
__device__ __forceinline__ uint32_t smem_u32(const void* p) {
    uint32_t a;
    asm("{ .reg .u64 t; cvta.to.shared.u64 t, %1; cvt.u32.u64 %0, t; }" : "=r"(a) : "l"(p));
    return a;
}
__device__ __forceinline__ uint32_t pack_f16x2(float a, float b) {
    uint32_t r;
    asm("cvt.rn.f16x2.f32 %0, %2, %1;" : "=r"(r) : "f"(a), "f"(b));
    return r;
}
__device__ __forceinline__ void ldsm_x4(uint32_t& a0, uint32_t& a1, uint32_t& a2,
                                        uint32_t& a3, uint32_t addr) {
    asm volatile("ldmatrix.sync.aligned.m8n8.x4.shared.b16 {%0,%1,%2,%3}, [%4];"
                 : "=r"(a0), "=r"(a1), "=r"(a2), "=r"(a3) : "r"(addr));
}
__device__ __forceinline__ void ldsm_x2(uint32_t& b0, uint32_t& b1, uint32_t addr) {
    asm volatile("ldmatrix.sync.aligned.m8n8.x2.shared.b16 {%0,%1}, [%2];"
                 : "=r"(b0), "=r"(b1) : "r"(addr));
}
__device__ __forceinline__ void mma16816(float& c0, float& c1, float& c2, float& c3,
                                         uint32_t a0, uint32_t a1, uint32_t a2, uint32_t a3,
                                         uint32_t b0, uint32_t b1) {
    asm volatile("mma.sync.aligned.m16n8k16.row.col.f32.f16.f16.f32 "
                 "{%0,%1,%2,%3}, {%4,%5,%6,%7}, {%8,%9}, {%0,%1,%2,%3};"
                 : "+f"(c0), "+f"(c1), "+f"(c2), "+f"(c3)
                 : "r"(a0), "r"(a1), "r"(a2), "r"(a3), "r"(b0), "r"(b1));
}

#define TSTR 72
#define WSTR 72

// ---------------------------------------------------------------------------
// Kernel 1: per-node u (bias folded) and v
// ---------------------------------------------------------------------------
__global__ void __launch_bounds__(256) k_prep(const float* __restrict__ x,
                                              const float* __restrict__ Wn2e,
                                              const float* __restrict__ bn2e) {
    int gid = blockIdx.x * 256 + threadIdx.x;
    if (gid >= NB * NN * NH) return;
    int node = gid >> 6;
    int h = gid & 63;
    float x0 = x[node * 2 + 0];
    float x1 = x[node * 2 + 1];
    const float* w = Wn2e + h * 4;
    g_u[gid] = bn2e[h] + w[0] * x0 + w[1] * x1;
    g_v[gid] =           w[2] * x0 + w[3] * x1;
}

// ---------------------------------------------------------------------------
// Kernel 2: edge GEMM via mma.sync m16n8k16. One CTA per (b,i), 256 thr.
// Warp tiling m32 x n32 (mq = w&3, nq = w>>2). B (W_e2e) fragments hoisted to
// registers once. Double-buffered T with prefetched v loads. Fused epilogue.
// ---------------------------------------------------------------------------
__global__ void __launch_bounds__(256, 2) k_edge_mma(const float* __restrict__ adj,
                                                     const float* __restrict__ We2e,
                                                     const float* __restrict__ be2e) {
    __shared__ __align__(16) __half Tsh[2][128 * TSTR];
    __shared__ __align__(16) __half Wsh[64 * WSTR];
    __shared__ float su[64];
    __shared__ float sb2[64];
    __shared__ float red[8][32];

    int t = threadIdx.x;
    int w = t >> 5;
    int lane = t & 31;
    int bi = blockIdx.x;
    int b = bi >> 9;
    int i = bi & 511;
    int mq = w & 3;          // m-block: j-rows [32*mq, 32*mq+32)
    int nq = w >> 2;         // n-block: h-cols [32*nq, 32*nq+32)

    uint32_t Tb0 = smem_u32(Tsh[0]);
    uint32_t Tb1 = smem_u32(Tsh[1]);
    uint32_t Wb = smem_u32(Wsh);

    // Stage W_e2e [64h][64k] as fp16 rows of stride WSTR.
    {
        int h = t >> 2;
        int kb = (t & 3) * 16;
        const float* wrow = We2e + h * 64 + kb;
        #pragma unroll
        for (int c = 0; c < 2; ++c) {
            float4 f0 = *(const float4*)(wrow + c * 8);
            float4 f1 = *(const float4*)(wrow + c * 8 + 4);
            uint4 pk;
            pk.x = pack_f16x2(f0.x, f0.y);
            pk.y = pack_f16x2(f0.z, f0.w);
            pk.z = pack_f16x2(f1.x, f1.y);
            pk.w = pack_f16x2(f1.z, f1.w);
            *(uint4*)(Wsh + h * WSTR + kb + c * 8) = pk;
        }
    }
    if (t < 64) {
        su[t]  = g_u[bi * 64 + t];
        sb2[t] = be2e[t];
    }
    __syncthreads();

    // Hoist B fragments: 16 ldmatrix for the whole kernel.
    uint32_t Bfr[4][4][2];
    #pragma unroll
    for (int k = 0; k < 4; ++k) {
        #pragma unroll
        for (int nt = 0; nt < 4; ++nt) {
            uint32_t addr = Wb + (uint32_t)(((nq * 32 + nt * 8 + (lane & 7)) * WSTR
                                             + k * 16 + ((lane >> 3) & 1) * 8) * 2);
            ldsm_x2(Bfr[k][nt][0], Bfr[k][nt][1], addr);
        }
    }

    const float* adjrow = adj + i * NN;
    const float* vbase = g_v + (b << 9) * 64;

    float sacc[8];
    #pragma unroll
    for (int q = 0; q < 8; ++q) sacc[q] = 0.f;

    int a_row = lane & 15;
    int a_kh = lane >> 4;
    int bj = t >> 1;              // j row this thread builds
    int bk = (t & 1) * 32;        // k-half this thread builds

    float4 vreg[8];
    // ---- prefetch + build tile 0 ----
    {
        const float* vrow = vbase + bj * 64 + bk;
        #pragma unroll
        for (int c = 0; c < 8; ++c) vreg[c] = *(const float4*)(vrow + c * 4);
        __half* trow = Tsh[0] + bj * TSTR + bk;
        #pragma unroll
        for (int c = 0; c < 4; ++c) {
            float4 f0 = vreg[2 * c], f1 = vreg[2 * c + 1];
            int k0 = bk + c * 8;
            uint4 pk;
            pk.x = pack_f16x2(fmaxf(su[k0 + 0] + f0.x, 0.f), fmaxf(su[k0 + 1] + f0.y, 0.f));
            pk.y = pack_f16x2(fmaxf(su[k0 + 2] + f0.z, 0.f), fmaxf(su[k0 + 3] + f0.w, 0.f));
            pk.z = pack_f16x2(fmaxf(su[k0 + 4] + f1.x, 0.f), fmaxf(su[k0 + 5] + f1.y, 0.f));
            pk.w = pack_f16x2(fmaxf(su[k0 + 6] + f1.z, 0.f), fmaxf(su[k0 + 7] + f1.w, 0.f));
            *(uint4*)(trow + c * 8) = pk;
        }
    }
    __syncthreads();

    #pragma unroll
    for (int jt = 0; jt < 4; ++jt) {
        int jbase = jt << 7;
        uint32_t Tcur = (jt & 1) ? Tb1 : Tb0;

        // prefetch v for next tile (LDG issued before MMA chain)
        if (jt < 3) {
            const float* vrow = vbase + ((jbase + 128) + bj) * 64 + bk;
            #pragma unroll
            for (int c = 0; c < 8; ++c) vreg[c] = *(const float4*)(vrow + c * 4);
        }

        // ---- MMA + fused epilogue, two m16 halves sequentially ----
        #pragma unroll
        for (int s = 0; s < 2; ++s) {
            float acc[4][4];
            #pragma unroll
            for (int nt = 0; nt < 4; ++nt) {
                acc[nt][0] = 0.f; acc[nt][1] = 0.f; acc[nt][2] = 0.f; acc[nt][3] = 0.f;
            }
            #pragma unroll
            for (int k = 0; k < 4; ++k) {
                uint32_t a0, a1, a2, a3;
                uint32_t a_addr = Tcur + (uint32_t)(((mq * 32 + s * 16 + a_row) * TSTR
                                                    + k * 16 + a_kh * 8) * 2);
                ldsm_x4(a0, a1, a2, a3, a_addr);
                #pragma unroll
                for (int nt = 0; nt < 4; ++nt)
                    mma16816(acc[nt][0], acc[nt][1], acc[nt][2], acc[nt][3],
                             a0, a1, a2, a3, Bfr[k][nt][0], Bfr[k][nt][1]);
            }
            // epilogue: relu(acc + b2) * adj[j], accumulate into sacc
            int r = jbase + mq * 32 + s * 16 + (lane >> 2);
            float aj0 = adjrow[r];
            float aj1 = adjrow[r + 8];
            #pragma unroll
            for (int nt = 0; nt < 4; ++nt) {
                int h0 = nq * 32 + nt * 8 + (lane & 3) * 2;
                float bb0 = sb2[h0];
                float bb1 = sb2[h0 + 1];
                sacc[nt * 2 + 0] += aj0 * fmaxf(acc[nt][0] + bb0, 0.f)
                                  + aj1 * fmaxf(acc[nt][2] + bb0, 0.f);
                sacc[nt * 2 + 1] += aj0 * fmaxf(acc[nt][1] + bb1, 0.f)
                                  + aj1 * fmaxf(acc[nt][3] + bb1, 0.f);
            }
        }

        // ---- pack prefetched v into the other buffer ----
        if (jt < 3) {
            __half* trow = ((jt & 1) ? Tsh[0] : Tsh[1]) + bj * TSTR + bk;
            #pragma unroll
            for (int c = 0; c < 4; ++c) {
                float4 f0 = vreg[2 * c], f1 = vreg[2 * c + 1];
                int k0 = bk + c * 8;
                uint4 pk;
                pk.x = pack_f16x2(fmaxf(su[k0 + 0] + f0.x, 0.f), fmaxf(su[k0 + 1] + f0.y, 0.f));
                pk.y = pack_f16x2(fmaxf(su[k0 + 2] + f0.z, 0.f), fmaxf(su[k0 + 3] + f0.w, 0.f));
                pk.z = pack_f16x2(fmaxf(su[k0 + 4] + f1.x, 0.f), fmaxf(su[k0 + 5] + f1.y, 0.f));
                pk.w = pack_f16x2(fmaxf(su[k0 + 6] + f1.z, 0.f), fmaxf(su[k0 + 7] + f1.w, 0.f));
                *(uint4*)(trow + c * 8) = pk;
            }
        }
        __syncthreads();
    }

    // ---- reduce over rows: lanes with equal (lane&3) hold the same h ----
    #pragma unroll
    for (int q = 0; q < 8; ++q) {
        sacc[q] += __shfl_down_sync(0xFFFFFFFFu, sacc[q], 16);
        sacc[q] += __shfl_down_sync(0xFFFFFFFFu, sacc[q], 8);
        sacc[q] += __shfl_down_sync(0xFFFFFFFFu, sacc[q], 4);
    }
    if (lane < 4) {
        #pragma unroll
        for (int nt = 0; nt < 4; ++nt) {
            red[w][nt * 8 + lane * 2 + 0] = sacc[nt * 2 + 0];
            red[w][nt * 8 + lane * 2 + 1] = sacc[nt * 2 + 1];
        }
    }
    __syncthreads();
    if (t < 64) {
        int nq2 = t >> 5;        // h-block
        int hh = t & 31;
        float s = red[nq2 * 4 + 0][hh] + red[nq2 * 4 + 1][hh]
                + red[nq2 * 4 + 2][hh] + red[nq2 * 4 + 3][hh];
        g_s[bi * 64 + t] = s;
    }
}

// ---------------------------------------------------------------------------
// Kernel 3: node head (unchanged)
// ---------------------------------------------------------------------------
__global__ void __launch_bounds__(256) k_node(const float* __restrict__ x,
                                              const float* __restrict__ We2n,
                                              const float* __restrict__ be2n,
                                              const float* __restrict__ Wn2n,
                                              const float* __restrict__ bn2n,
                                              const float* __restrict__ Wo1,
                                              const float* __restrict__ bo1,
                                              const float* __restrict__ Wo2,
                                              const float* __restrict__ bo2,
                                              float* __restrict__ out) {
    __shared__ float wbuf[66 * 64];
    __shared__ float bufA[16][64];
    __shared__ float bufB[16][64];
    __shared__ float sx[16][2];

    int t = threadIdx.x;
    int g = t >> 6;
    int h = t & 63;
    int nbase = blockIdx.x * 16;

    for (int n = g; n < 16; n += 4) bufA[n][h] = g_s[(nbase + n) * 64 + h];
    if (t < 32) sx[t >> 1][t & 1] = x[(nbase + (t >> 1)) * 2 + (t & 1)];

    for (int idx = t; idx < 64 * 64; idx += 256)
        wbuf[(idx & 63) * 64 + (idx >> 6)] = We2n[idx];
    __syncthreads();
    {
        float bh = be2n[h];
        for (int n = g; n < 16; n += 4) {
            float acc = bh;
            #pragma unroll 8
            for (int k = 0; k < 64; ++k) acc += wbuf[k * 64 + h] * bufA[n][k];
            bufB[n][h] = fmaxf(acc, 0.f);
        }
    }
    __syncthreads();

    for (int idx = t; idx < 64 * 64; idx += 256)
        wbuf[(idx & 63) * 64 + (idx >> 6)] = Wn2n[idx];
    __syncthreads();
    {
        float bh = bn2n[h];
        for (int n = g; n < 16; n += 4) {
            float acc = bh;
            #pragma unroll 8
            for (int k = 0; k < 64; ++k) acc += wbuf[k * 64 + h] * bufB[n][k];
            bufA[n][h] = fmaxf(acc, 0.f);
        }
    }
    __syncthreads();

    for (int idx = t; idx < 66 * 64; idx += 256)
        wbuf[(idx % 66) * 64 + (idx / 66)] = Wo1[idx];
    __syncthreads();
    {
        float bh = bo1[h];
        for (int n = g; n < 16; n += 4) {
            float acc = bh + wbuf[0 * 64 + h] * sx[n][0]
                          + wbuf[1 * 64 + h] * sx[n][1];
            #pragma unroll 8
            for (int k = 0; k < 64; ++k) acc += wbuf[(k + 2) * 64 + h] * bufA[n][k];
            bufB[n][h] = fmaxf(acc, 0.f);
        }
    }
    __syncthreads();

    if (t < 32) {
        int n = t >> 1;
        int o = t & 1;
        float acc = bo2[o];
        const float* wv = Wo2 + o * 64;
        #pragma unroll 8
        for (int k = 0; k < 64; ++k) acc += wv[k] * bufB[n][k];
        out[(nbase + n) * 2 + o] = acc;
    }
}

// ---------------------------------------------------------------------------
extern "C" void kernel_launch(void* const* d_in, const int* in_sizes, int n_in,
                              void* d_out, int out_size) {
    const float* input = (const float*)d_in[0];
    const float* adj   = (const float*)d_in[1];
    const float* W_n2e = (const float*)d_in[2];
    const float* b_n2e = (const float*)d_in[3];
    const float* W_e2e = (const float*)d_in[4];
    const float* b_e2e = (const float*)d_in[5];
    const float* W_e2n = (const float*)d_in[6];
    const float* b_e2n = (const float*)d_in[7];
    const float* W_n2n = (const float*)d_in[8];
    const float* b_n2n = (const float*)d_in[9];
    const float* W_o1  = (const float*)d_in[10];
    const float* b_o1  = (const float*)d_in[11];
    const float* W_o2  = (const float*)d_in[12];
    const float* b_o2  = (const float*)d_in[13];
    float* out = (float*)d_out;

    k_prep<<<(NB * NN * NH + 255) / 256, 256>>>(input, W_n2e, b_n2e);
    k_edge_mma<<<NB * NN, 256>>>(adj, W_e2e, b_e2e);
    k_node<<<NB * NN / 16, 256>>>(input, W_e2n, b_e2n, W_n2n, b_n2n,
                                  W_o1, b_o1, W_o2, b_o2, out);
}

// round 8
// speedup vs baseline: 3.3374x; 1.8068x over previous
#include <cuda_runtime.h>
#include <cuda_fp16.h>
#include <cstdint>

// Shapes (fixed)
#define NB 4
#define NN 512
#define ND 2
#define NH 64
#define NO 2

// Scratch (only s now)
__device__ float g_s[NB * NN * NH];

// ---------------------------------------------------------------------------
__device__ __forceinline__ uint32_t smem_u32(const void* p) {
    uint32_t a;
    asm("{ .reg .u64 t; cvta.to.shared.u64 t, %1; cvt.u32.u64 %0, t; }" : "=r"(a) : "l"(p));
    return a;
}
__device__ __forceinline__ uint32_t pack_f16x2(float a, float b) {
    uint32_t r;
    asm("cvt.rn.f16x2.f32 %0, %2, %1;" : "=r"(r) : "f"(a), "f"(b));
    return r;
}
__device__ __forceinline__ void ldsm_x4(uint32_t& a0, uint32_t& a1, uint32_t& a2,
                                        uint32_t& a3, uint32_t addr) {
    asm volatile("ldmatrix.sync.aligned.m8n8.x4.shared.b16 {%0,%1,%2,%3}, [%4];"
                 : "=r"(a0), "=r"(a1), "=r"(a2), "=r"(a3) : "r"(addr));
}
__device__ __forceinline__ void ldsm_x2(uint32_t& b0, uint32_t& b1, uint32_t addr) {
    asm volatile("ldmatrix.sync.aligned.m8n8.x2.shared.b16 {%0,%1}, [%2];"
                 : "=r"(b0), "=r"(b1) : "r"(addr));
}
__device__ __forceinline__ void mma16816(float& c0, float& c1, float& c2, float& c3,
                                         uint32_t a0, uint32_t a1, uint32_t a2, uint32_t a3,
                                         uint32_t b0, uint32_t b1) {
    asm volatile("mma.sync.aligned.m16n8k16.row.col.f32.f16.f16.f32 "
                 "{%0,%1,%2,%3}, {%4,%5,%6,%7}, {%8,%9}, {%0,%1,%2,%3};"
                 : "+f"(c0), "+f"(c1), "+f"(c2), "+f"(c3)
                 : "r"(a0), "r"(a1), "r"(a2), "r"(a3), "r"(b0), "r"(b1));
}

#define TSTR 72
#define WSTR 72

// ---------------------------------------------------------------------------
// Edge kernel: one CTA per (b,i), 256 thr. No k_prep, no g_u/g_v:
// v is recomputed from x in registers (2 FFMA per element) — zero LDG in the
// main loop. Warp tiling m32 x n32, B fragments hoisted, fused epilogue.
// ---------------------------------------------------------------------------
__global__ void __launch_bounds__(256, 2) k_edge_mma(const float* __restrict__ x,
                                                     const float* __restrict__ adj,
                                                     const float* __restrict__ Wn2e,
                                                     const float* __restrict__ bn2e,
                                                     const float* __restrict__ We2e,
                                                     const float* __restrict__ be2e) {
    // sx (512*2 floats = 4KB) aliases Wsh (9216B): W is dead after B-hoist.
    __shared__ __align__(16) __half Tsh[2][128 * TSTR];
    __shared__ __align__(16) char wpool[64 * WSTR * 2];   // Wsh then sx
    __shared__ float su[64];
    __shared__ float sb2[64];
    __shared__ float red[8][32];

    __half* Wsh = (__half*)wpool;
    float* sx = (float*)wpool;      // [512][2] after hoist

    int t = threadIdx.x;
    int w = t >> 5;
    int lane = t & 31;
    int bi = blockIdx.x;
    int b = bi >> 9;
    int i = bi & 511;
    int mq = w & 3;          // m-block: j-rows [32*mq, 32*mq+32)
    int nq = w >> 2;         // n-block: h-cols [32*nq, 32*nq+32)

    uint32_t Tb0 = smem_u32(Tsh[0]);
    uint32_t Tb1 = smem_u32(Tsh[1]);
    uint32_t Wb = smem_u32(wpool);

    // ---- stage W_e2e [64h][64k] as fp16, rows of stride WSTR ----
    {
        int h = t >> 2;
        int kb = (t & 3) * 16;
        const float* wrow = We2e + h * 64 + kb;
        #pragma unroll
        for (int c = 0; c < 2; ++c) {
            float4 f0 = *(const float4*)(wrow + c * 8);
            float4 f1 = *(const float4*)(wrow + c * 8 + 4);
            uint4 pk;
            pk.x = pack_f16x2(f0.x, f0.y);
            pk.y = pack_f16x2(f0.z, f0.w);
            pk.z = pack_f16x2(f1.x, f1.y);
            pk.w = pack_f16x2(f1.z, f1.w);
            *(uint4*)(Wsh + h * WSTR + kb + c * 8) = pk;
        }
    }
    // u_i[k] = b1[k] + W[k][0]*xi0 + W[k][1]*xi1  (threads 0..63)
    if (t < 64) {
        float4 wr = *(const float4*)(Wn2e + t * 4);
        float xi0 = x[(b * NN + i) * 2 + 0];
        float xi1 = x[(b * NN + i) * 2 + 1];
        su[t]  = bn2e[t] + wr.x * xi0 + wr.y * xi1;
        sb2[t] = be2e[t];
    }
    __syncthreads();

    // ---- hoist B fragments: 16 ldmatrix total ----
    uint32_t Bfr[4][4][2];
    #pragma unroll
    for (int k = 0; k < 4; ++k) {
        #pragma unroll
        for (int nt = 0; nt < 4; ++nt) {
            uint32_t addr = Wb + (uint32_t)(((nq * 32 + nt * 8 + (lane & 7)) * WSTR
                                             + k * 16 + ((lane >> 3) & 1) * 8) * 2);
            ldsm_x2(Bfr[k][nt][0], Bfr[k][nt][1], addr);
        }
    }
    __syncthreads();   // Wsh dead; safe to overwrite with sx

    // ---- stage x for the whole batch row-space (512 nodes, 2 floats) ----
    {
        const float* xb = x + b * NN * 2;
        for (int idx = t; idx < NN * 2 / 4; idx += 256)
            ((float4*)sx)[idx] = ((const float4*)xb)[idx];
    }

    // ---- per-thread build constants: this thread owns k-octet (t&7)*8 ----
    int ko = (t & 7) * 8;
    int jrow4 = (t >> 3) * 4;     // 4 j rows: jrow4..jrow4+3 within tile
    float w2r[8], w3r[8], ur[8];
    {
        #pragma unroll
        for (int kk = 0; kk < 8; ++kk) {
            float4 wr = *(const float4*)(Wn2e + (ko + kk) * 4);
            w2r[kk] = wr.z;
            w3r[kk] = wr.w;
        }
    }
    __syncthreads();   // sx staged (and su visible)
    #pragma unroll
    for (int kk = 0; kk < 8; ++kk) ur[kk] = su[ko + kk];

    const float* adjrow = adj + i * NN;

    float sacc[8];
    #pragma unroll
    for (int q = 0; q < 8; ++q) sacc[q] = 0.f;

    int a_row = lane & 15;
    int a_kh = lane >> 4;

    // ---- build tile 0 ----
    {
        __half* tb = Tsh[0];
        #pragma unroll
        for (int jj = 0; jj < 4; ++jj) {
            int j = jrow4 + jj;
            float x0 = sx[j * 2 + 0];
            float x1 = sx[j * 2 + 1];
            uint4 pk;
            float r0 = fmaxf(fmaf(w3r[0], x1, fmaf(w2r[0], x0, ur[0])), 0.f);
            float r1 = fmaxf(fmaf(w3r[1], x1, fmaf(w2r[1], x0, ur[1])), 0.f);
            float r2 = fmaxf(fmaf(w3r[2], x1, fmaf(w2r[2], x0, ur[2])), 0.f);
            float r3 = fmaxf(fmaf(w3r[3], x1, fmaf(w2r[3], x0, ur[3])), 0.f);
            float r4 = fmaxf(fmaf(w3r[4], x1, fmaf(w2r[4], x0, ur[4])), 0.f);
            float r5 = fmaxf(fmaf(w3r[5], x1, fmaf(w2r[5], x0, ur[5])), 0.f);
            float r6 = fmaxf(fmaf(w3r[6], x1, fmaf(w2r[6], x0, ur[6])), 0.f);
            float r7 = fmaxf(fmaf(w3r[7], x1, fmaf(w2r[7], x0, ur[7])), 0.f);
            pk.x = pack_f16x2(r0, r1);
            pk.y = pack_f16x2(r2, r3);
            pk.z = pack_f16x2(r4, r5);
            pk.w = pack_f16x2(r6, r7);
            *(uint4*)(tb + j * TSTR + ko) = pk;
        }
    }
    __syncthreads();

    #pragma unroll
    for (int jt = 0; jt < 4; ++jt) {
        int jbase = jt << 7;
        uint32_t Tcur = (jt & 1) ? Tb1 : Tb0;

        // ---- MMA + fused epilogue, two m16 halves ----
        #pragma unroll
        for (int s = 0; s < 2; ++s) {
            float acc[4][4];
            #pragma unroll
            for (int nt = 0; nt < 4; ++nt) {
                acc[nt][0] = 0.f; acc[nt][1] = 0.f; acc[nt][2] = 0.f; acc[nt][3] = 0.f;
            }
            #pragma unroll
            for (int k = 0; k < 4; ++k) {
                uint32_t a0, a1, a2, a3;
                uint32_t a_addr = Tcur + (uint32_t)(((mq * 32 + s * 16 + a_row) * TSTR
                                                    + k * 16 + a_kh * 8) * 2);
                ldsm_x4(a0, a1, a2, a3, a_addr);
                #pragma unroll
                for (int nt = 0; nt < 4; ++nt)
                    mma16816(acc[nt][0], acc[nt][1], acc[nt][2], acc[nt][3],
                             a0, a1, a2, a3, Bfr[k][nt][0], Bfr[k][nt][1]);
            }
            int r = jbase + mq * 32 + s * 16 + (lane >> 2);
            float aj0 = adjrow[r];
            float aj1 = adjrow[r + 8];
            #pragma unroll
            for (int nt = 0; nt < 4; ++nt) {
                int h0 = nq * 32 + nt * 8 + (lane & 3) * 2;
                float bb0 = sb2[h0];
                float bb1 = sb2[h0 + 1];
                sacc[nt * 2 + 0] += aj0 * fmaxf(acc[nt][0] + bb0, 0.f)
                                  + aj1 * fmaxf(acc[nt][2] + bb0, 0.f);
                sacc[nt * 2 + 1] += aj0 * fmaxf(acc[nt][1] + bb1, 0.f)
                                  + aj1 * fmaxf(acc[nt][3] + bb1, 0.f);
            }
        }

        // ---- build next tile into the other buffer (pure compute) ----
        if (jt < 3) {
            __half* tb = (jt & 1) ? Tsh[0] : Tsh[1];
            int jb = jbase + 128;
            #pragma unroll
            for (int jj = 0; jj < 4; ++jj) {
                int j = jrow4 + jj;
                float x0 = sx[(jb + j) * 2 + 0];
                float x1 = sx[(jb + j) * 2 + 1];
                uint4 pk;
                float r0 = fmaxf(fmaf(w3r[0], x1, fmaf(w2r[0], x0, ur[0])), 0.f);
                float r1 = fmaxf(fmaf(w3r[1], x1, fmaf(w2r[1], x0, ur[1])), 0.f);
                float r2 = fmaxf(fmaf(w3r[2], x1, fmaf(w2r[2], x0, ur[2])), 0.f);
                float r3 = fmaxf(fmaf(w3r[3], x1, fmaf(w2r[3], x0, ur[3])), 0.f);
                float r4 = fmaxf(fmaf(w3r[4], x1, fmaf(w2r[4], x0, ur[4])), 0.f);
                float r5 = fmaxf(fmaf(w3r[5], x1, fmaf(w2r[5], x0, ur[5])), 0.f);
                float r6 = fmaxf(fmaf(w3r[6], x1, fmaf(w2r[6], x0, ur[6])), 0.f);
                float r7 = fmaxf(fmaf(w3r[7], x1, fmaf(w2r[7], x0, ur[7])), 0.f);
                pk.x = pack_f16x2(r0, r1);
                pk.y = pack_f16x2(r2, r3);
                pk.z = pack_f16x2(r4, r5);
                pk.w = pack_f16x2(r6, r7);
                *(uint4*)(tb + j * TSTR + ko) = pk;
            }
        }
        __syncthreads();
    }

    // ---- reduce ----
    #pragma unroll
    for (int q = 0; q < 8; ++q) {
        sacc[q] += __shfl_down_sync(0xFFFFFFFFu, sacc[q], 16);
        sacc[q] += __shfl_down_sync(0xFFFFFFFFu, sacc[q], 8);
        sacc[q] += __shfl_down_sync(0xFFFFFFFFu, sacc[q], 4);
    }
    if (lane < 4) {
        #pragma unroll
        for (int nt = 0; nt < 4; ++nt) {
            red[w][nt * 8 + lane * 2 + 0] = sacc[nt * 2 + 0];
            red[w][nt * 8 + lane * 2 + 1] = sacc[nt * 2 + 1];
        }
    }
    __syncthreads();
    if (t < 64) {
        int nq2 = t >> 5;
        int hh = t & 31;
        g_s[bi * 64 + t] = red[nq2 * 4 + 0][hh] + red[nq2 * 4 + 1][hh]
                         + red[nq2 * 4 + 2][hh] + red[nq2 * 4 + 3][hh];
    }
}

// ---------------------------------------------------------------------------
// Node head (unchanged)
// ---------------------------------------------------------------------------
__global__ void __launch_bounds__(256) k_node(const float* __restrict__ x,
                                              const float* __restrict__ We2n,
                                              const float* __restrict__ be2n,
                                              const float* __restrict__ Wn2n,
                                              const float* __restrict__ bn2n,
                                              const float* __restrict__ Wo1,
                                              const float* __restrict__ bo1,
                                              const float* __restrict__ Wo2,
                                              const float* __restrict__ bo2,
                                              float* __restrict__ out) {
    __shared__ float wbuf[66 * 64];
    __shared__ float bufA[16][64];
    __shared__ float bufB[16][64];
    __shared__ float sx[16][2];

    int t = threadIdx.x;
    int g = t >> 6;
    int h = t & 63;
    int nbase = blockIdx.x * 16;

    for (int n = g; n < 16; n += 4) bufA[n][h] = g_s[(nbase + n) * 64 + h];
    if (t < 32) sx[t >> 1][t & 1] = x[(nbase + (t >> 1)) * 2 + (t & 1)];

    for (int idx = t; idx < 64 * 64; idx += 256)
        wbuf[(idx & 63) * 64 + (idx >> 6)] = We2n[idx];
    __syncthreads();
    {
        float bh = be2n[h];
        for (int n = g; n < 16; n += 4) {
            float acc = bh;
            #pragma unroll 8
            for (int k = 0; k < 64; ++k) acc += wbuf[k * 64 + h] * bufA[n][k];
            bufB[n][h] = fmaxf(acc, 0.f);
        }
    }
    __syncthreads();

    for (int idx = t; idx < 64 * 64; idx += 256)
        wbuf[(idx & 63) * 64 + (idx >> 6)] = Wn2n[idx];
    __syncthreads();
    {
        float bh = bn2n[h];
        for (int n = g; n < 16; n += 4) {
            float acc = bh;
            #pragma unroll 8
            for (int k = 0; k < 64; ++k) acc += wbuf[k * 64 + h] * bufB[n][k];
            bufA[n][h] = fmaxf(acc, 0.f);
        }
    }
    __syncthreads();

    for (int idx = t; idx < 66 * 64; idx += 256)
        wbuf[(idx % 66) * 64 + (idx / 66)] = Wo1[idx];
    __syncthreads();
    {
        float bh = bo1[h];
        for (int n = g; n < 16; n += 4) {
            float acc = bh + wbuf[0 * 64 + h] * sx[n][0]
                          + wbuf[1 * 64 + h] * sx[n][1];
            #pragma unroll 8
            for (int k = 0; k < 64; ++k) acc += wbuf[(k + 2) * 64 + h] * bufA[n][k];
            bufB[n][h] = fmaxf(acc, 0.f);
        }
    }
    __syncthreads();

    if (t < 32) {
        int n = t >> 1;
        int o = t & 1;
        float acc = bo2[o];
        const float* wv = Wo2 + o * 64;
        #pragma unroll 8
        for (int k = 0; k < 64; ++k) acc += wv[k] * bufB[n][k];
        out[(nbase + n) * 2 + o] = acc;
    }
}

// ---------------------------------------------------------------------------
extern "C" void kernel_launch(void* const* d_in, const int* in_sizes, int n_in,
                              void* d_out, int out_size) {
    const float* input = (const float*)d_in[0];
    const float* adj   = (const float*)d_in[1];
    const float* W_n2e = (const float*)d_in[2];
    const float* b_n2e = (const float*)d_in[3];
    const float* W_e2e = (const float*)d_in[4];
    const float* b_e2e = (const float*)d_in[5];
    const float* W_e2n = (const float*)d_in[6];
    const float* b_e2n = (const float*)d_in[7];
    const float* W_n2n = (const float*)d_in[8];
    const float* b_n2n = (const float*)d_in[9];
    const float* W_o1  = (const float*)d_in[10];
    const float* b_o1  = (const float*)d_in[11];
    const float* W_o2  = (const float*)d_in[12];
    const float* b_o2  = (const float*)d_in[13];
    float* out = (float*)d_out;

    k_edge_mma<<<NB * NN, 256>>>(input, adj, W_n2e, b_n2e, W_e2e, b_e2e);
    k_node<<<NB * NN / 16, 256>>>(input, W_e2n, b_e2n, W_n2n, b_n2n,
                                  W_o1, b_o1, W_o2, b_o2, out);
}